// round 2
// baseline (speedup 1.0000x reference)
#include <cuda_runtime.h>
#include <math.h>

#define Bsz   64
#define Tlen  256
#define Din   128
#define Hd    1024
#define Ld    5
#define Cd    10
#define FourH 4096
#define Mrows (Tlen * Bsz)   // 16384

// ---------------- scratch (static device globals; no allocs) ----------------
__device__ float g_xproj[(size_t)Mrows * FourH];   // 256 MB: per-layer input projection (+bias)
__device__ float g_hseq0[(size_t)Mrows * Hd];      // 64 MB: hidden sequence ping
__device__ float g_hseq1[(size_t)Mrows * Hd];      // 64 MB: hidden sequence pong
__device__ float g_h0[Bsz * Hd];                   // h double buffer
__device__ float g_h1[Bsz * Hd];
__device__ float g_c[Bsz * Hd];                    // cell state (column-private per block)
__device__ unsigned g_bar[2];                      // [0]=arrive count, [1]=release flag

// ---------------- software grid barrier (all CTAs resident by construction) ----
__device__ __forceinline__ void grid_sync(unsigned epoch, unsigned nblk) {
    __syncthreads();
    if (threadIdx.x == 0) {
        __threadfence();
        unsigned prev = atomicAdd(&g_bar[0], 1u);
        if (prev == nblk * epoch - 1u) {
            atomicExch(&g_bar[1], epoch);
        } else {
            while (atomicAdd(&g_bar[1], 0u) < epoch) { }
        }
        __threadfence();
    }
    __syncthreads();
}

// ---------------- input projection GEMM ----------------
// g_xproj[r][n] = bias[n] + sum_k A[r][k] * W[k][n]; row r = t*Bsz + b
__global__ __launch_bounds__(256) void proj_gemm(
    const float* __restrict__ x_ext, int src_sel,
    int stride_t, int stride_b, int K,
    const float* __restrict__ W, const float* __restrict__ bias)
{
    const float* A = (src_sel == 0) ? x_ext : (src_sel == 1 ? g_hseq0 : g_hseq1);
    __shared__ float As[8][128];
    __shared__ float Bs2[8][128];

    int tid  = threadIdx.x;
    int row0 = blockIdx.y * 128;
    int col0 = blockIdx.x * 128;

    float acc[8][8];
#pragma unroll
    for (int i = 0; i < 8; i++)
#pragma unroll
        for (int j = 0; j < 8; j++) acc[i][j] = 0.f;

    int mb = (tid >> 4) * 8;
    int nb = (tid & 15) * 8;

    int lr = tid >> 1;
    int lk = (tid & 1) * 4;
    int grow = row0 + lr;
    const float* Arow = A + (size_t)(grow >> 6) * stride_t + (size_t)(grow & 63) * stride_b;

    int bk = tid >> 5;
    int bn = (tid & 31) * 4;

    for (int k0 = 0; k0 < K; k0 += 8) {
        float4 av = *(const float4*)(Arow + k0 + lk);
        As[lk + 0][lr] = av.x;
        As[lk + 1][lr] = av.y;
        As[lk + 2][lr] = av.z;
        As[lk + 3][lr] = av.w;
        *(float4*)&Bs2[bk][bn] = *(const float4*)(W + (size_t)(k0 + bk) * FourH + col0 + bn);
        __syncthreads();
#pragma unroll
        for (int k = 0; k < 8; k++) {
            float a[8], b[8];
            *(float4*)&a[0] = *(const float4*)&As[k][mb];
            *(float4*)&a[4] = *(const float4*)&As[k][mb + 4];
            *(float4*)&b[0] = *(const float4*)&Bs2[k][nb];
            *(float4*)&b[4] = *(const float4*)&Bs2[k][nb + 4];
#pragma unroll
            for (int i = 0; i < 8; i++)
#pragma unroll
                for (int j = 0; j < 8; j++) acc[i][j] += a[i] * b[j];
        }
        __syncthreads();
    }

#pragma unroll
    for (int i = 0; i < 8; i++) {
        size_t r = (size_t)(row0 + mb + i);
        float* o = g_xproj + r * FourH + col0 + nb;
#pragma unroll
        for (int j = 0; j < 8; j++) o[j] = acc[i][j] + bias[col0 + nb + j];
    }
}

// ---------------- persistent recurrent layer: all 256 timesteps in one launch ----
// 128 blocks x 256 threads. Block owns 8 h-cols (=> 32 z-cols), caches its
// 1024x32 Wh slice in smem (128 KB). Grid barrier between timesteps.
// smem layout: w_s[1024*32] | sh_h[64*33] | sh_z[64*33]
#define SMEM_WS   (1024 * 32)
#define SMEM_HST  (64 * 33)
#define SMEM_BYTES ((SMEM_WS + 2 * SMEM_HST) * (int)sizeof(float))

__global__ __launch_bounds__(256) void lstm_layer_persistent(
    const float* __restrict__ Wh, int seqsel, int writeseq)
{
    extern __shared__ float smem[];
    float* w_s  = smem;
    float* sh_h = smem + SMEM_WS;
    float* sh_z = sh_h + SMEM_HST;

    int tid = threadIdx.x;
    int c0  = blockIdx.x * 8;          // h-column base
    unsigned nblk = gridDim.x;

    // load Wh slice into smem: w_s[k*32 + (gate*8+col)]
    for (int idx = tid; idx < SMEM_WS; idx += 256) {
        int k = idx >> 5, n = idx & 31;
        int gate = n >> 3, col = n & 7;
        w_s[idx] = Wh[(size_t)k * FourH + gate * Hd + c0 + col];
    }
    // zero own state columns
    for (int idx = tid; idx < 512; idx += 256) {
        int mm = idx >> 3, col = idx & 7;
        int hi = mm * Hd + c0 + col;
        g_c[hi] = 0.f; g_h0[hi] = 0.f; g_h1[hi] = 0.f;
    }
    unsigned epoch = 0;
    grid_sync(++epoch, nblk);

    float* seq = seqsel ? g_hseq1 : g_hseq0;
    int m  = tid & 31;                 // rows m and m+32
    int nb = (tid >> 5) * 4;           // 4 local z-columns (const per warp -> LDS broadcast)

    for (int t = 0; t < Tlen; t++) {
        const float* h_in  = (t & 1) ? g_h1 : g_h0;
        float*       h_out = (t & 1) ? g_h0 : g_h1;

        float acc[8];
#pragma unroll
        for (int j = 0; j < 8; j++) acc[j] = 0.f;

        for (int k0 = 0; k0 < Hd; k0 += 32) {
#pragma unroll
            for (int i = 0; i < 8; i++) {
                int idx = tid + 256 * i;
                int r = idx >> 5, c = idx & 31;
                sh_h[r * 33 + c] = h_in[r * Hd + k0 + c];
            }
            __syncthreads();
#pragma unroll
            for (int k = 0; k < 32; k++) {
                float a0 = sh_h[m * 33 + k];
                float a1 = sh_h[(m + 32) * 33 + k];
                float4 bv = *(const float4*)&w_s[(k0 + k) * 32 + nb];
                acc[0] += a0 * bv.x; acc[1] += a0 * bv.y;
                acc[2] += a0 * bv.z; acc[3] += a0 * bv.w;
                acc[4] += a1 * bv.x; acc[5] += a1 * bv.y;
                acc[6] += a1 * bv.z; acc[7] += a1 * bv.w;
            }
            __syncthreads();
        }

#pragma unroll
        for (int j = 0; j < 4; j++) {
            sh_z[m * 33 + nb + j]        = acc[j];
            sh_z[(m + 32) * 33 + nb + j] = acc[4 + j];
        }
        __syncthreads();

        // gate phase: 512 (row,col) items, 2 per thread
#pragma unroll
        for (int p = 0; p < 2; p++) {
            int idx = tid * 2 + p;
            int col = idx & 7;
            int mm  = idx >> 3;
            const float* xp = g_xproj + (size_t)(t * Bsz + mm) * FourH + c0 + col;
            float zi = sh_z[mm * 33 + col]      + xp[0];
            float zf = sh_z[mm * 33 + 8 + col]  + xp[Hd];
            float zg = sh_z[mm * 33 + 16 + col] + xp[2 * Hd];
            float zo = sh_z[mm * 33 + 24 + col] + xp[3 * Hd];

            int hi = mm * Hd + c0 + col;
            float co = g_c[hi];
            float si = 1.f / (1.f + expf(-zi));
            float sf = 1.f / (1.f + expf(-zf));
            float so = 1.f / (1.f + expf(-zo));
            float tg = tanhf(zg);
            float cn = sf * co + si * tg;
            float hn = so * tanhf(cn);

            g_c[hi]   = cn;
            h_out[hi] = hn;
            if (writeseq)
                seq[(size_t)(t * Bsz + mm) * Hd + c0 + col] = hn;
        }
        grid_sync(++epoch, nblk);
    }
}

// ---------------- head: out[b][c] = h_final[b] . W_head[:,c] + b_head[c] ----------------
__global__ void head_kernel(const float* __restrict__ Wc, const float* __restrict__ bc,
                            float* __restrict__ out)
{
    int b = blockIdx.x;
    int w = threadIdx.x >> 5;   // class index 0..9 (320 threads = 10 warps)
    int lane = threadIdx.x & 31;
    const float* h = g_h0 + b * Hd;   // t=255 (odd) writes buffer 0
    float s = 0.f;
    for (int k = lane; k < Hd; k += 32) s += h[k] * Wc[k * Cd + w];
#pragma unroll
    for (int o = 16; o > 0; o >>= 1) s += __shfl_down_sync(0xffffffffu, s, o);
    if (lane == 0) out[b * Cd + w] = s + bc[w];
}

// ---------------- launch ----------------
extern "C" void kernel_launch(void* const* d_in, const int* in_sizes, int n_in,
                              void* d_out, int out_size)
{
    const float* x    = (const float*)d_in[0];  // [B,T,D]
    const float* Wx0  = (const float*)d_in[1];  // [D,4H]
    const float* Wxs  = (const float*)d_in[2];  // [L-1,H,4H]
    const float* Whs  = (const float*)d_in[3];  // [L,H,4H]
    const float* bs   = (const float*)d_in[4];  // [L,4H]
    const float* Wc   = (const float*)d_in[5];  // [H,C]
    const float* bc   = (const float*)d_in[6];  // [C]
    float* out = (float*)d_out;

    cudaFuncSetAttribute(lstm_layer_persistent,
                         cudaFuncAttributeMaxDynamicSharedMemorySize, SMEM_BYTES);

    void* bar_addr = nullptr;
    cudaGetSymbolAddress(&bar_addr, g_bar);

    dim3 pgrid(FourH / 128, Mrows / 128);   // 32 x 128

    for (int l = 0; l < Ld; l++) {
        int src = (l == 0) ? 0 : ((((l - 1) & 1) == 0) ? 1 : 2);
        const float* W = (l == 0) ? Wx0 : (Wxs + (size_t)(l - 1) * Hd * FourH);
        int K  = (l == 0) ? Din : Hd;
        int st = (l == 0) ? Din : Bsz * Hd;       // stride for t within a row index
        int sb = (l == 0) ? Tlen * Din : Hd;      // stride for b within a row index

        proj_gemm<<<pgrid, 256>>>(x, src, st, sb, K, W, bs + (size_t)l * FourH);

        cudaMemsetAsync(bar_addr, 0, 2 * sizeof(unsigned));  // reset barrier state

        const float* Wh = Whs + (size_t)l * Hd * FourH;
        lstm_layer_persistent<<<128, 256, SMEM_BYTES>>>(Wh, l & 1, (l < Ld - 1) ? 1 : 0);
    }

    head_kernel<<<Bsz, 320>>>(Wc, bc, out);
}

// round 3
// speedup vs baseline: 1.4823x; 1.4823x over previous
#include <cuda_runtime.h>
#include <math.h>

#define Bsz   64
#define Tlen  256
#define Din   128
#define Hd    1024
#define Ld    5
#define Cd    10
#define FourH 4096
#define Mrows (Tlen * Bsz)   // 16384

typedef unsigned long long ull;

// ---------------- f32x2 helpers ----------------
__device__ __forceinline__ ull dup2(float v) {
    ull r; asm("mov.b64 %0, {%1, %1};" : "=l"(r) : "f"(v)); return r;
}
__device__ __forceinline__ ull fma2(ull a, ull b, ull c) {
    ull d; asm("fma.rn.f32x2 %0, %1, %2, %3;" : "=l"(d) : "l"(a), "l"(b), "l"(c)); return d;
}
__device__ __forceinline__ ull add2(ull a, ull b) {
    ull d; asm("add.rn.f32x2 %0, %1, %2;" : "=l"(d) : "l"(a), "l"(b)); return d;
}
__device__ __forceinline__ void unpack2(ull v, float& lo, float& hi) {
    asm("mov.b64 {%0, %1}, %2;" : "=f"(lo), "=f"(hi) : "l"(v));
}

// ---------------- scratch (static device globals; no allocs) ----------------
__device__ float g_xproj[(size_t)Mrows * FourH];   // 256 MB
__device__ float g_hseq0[(size_t)Mrows * Hd];      // 64 MB
__device__ float g_hseq1[(size_t)Mrows * Hd];      // 64 MB
__device__ float g_h0[Bsz * Hd];
__device__ float g_h1[Bsz * Hd];
__device__ float g_c[Bsz * Hd];
__device__ unsigned g_bar[2];                      // [0]=arrive, [1]=release

// ---------------- software grid barrier ----------------
__device__ __forceinline__ void grid_sync(unsigned epoch, unsigned nblk) {
    __syncthreads();
    if (threadIdx.x == 0) {
        __threadfence();
        unsigned prev = atomicAdd(&g_bar[0], 1u);
        if (prev == nblk * epoch - 1u) {
            asm volatile("st.release.gpu.global.u32 [%0], %1;" :: "l"(&g_bar[1]), "r"(epoch) : "memory");
        } else {
            unsigned v;
            do {
                asm volatile("ld.acquire.gpu.global.u32 %0, [%1];" : "=r"(v) : "l"(&g_bar[1]) : "memory");
            } while (v < epoch);
        }
    }
    __syncthreads();
}

// ---------------- fast activations ----------------
__device__ __forceinline__ float sigmoid_f(float x) {
    return __fdividef(1.f, 1.f + __expf(-x));
}
__device__ __forceinline__ float tanh_f(float x) {
    float e = __expf(2.f * x);
    return 1.f - __fdividef(2.f, e + 1.f);
}

// ---------------- input projection GEMM (f32x2) ----------------
// g_xproj[r][n] = bias[n] + sum_k A[r][k] * W[k][n]; row r = t*Bsz + b
__global__ __launch_bounds__(256) void proj_gemm(
    const float* __restrict__ x_ext, int src_sel,
    int stride_t, int stride_b, int K,
    const float* __restrict__ W, const float* __restrict__ bias)
{
    const float* A = (src_sel == 0) ? x_ext : (src_sel == 1 ? g_hseq0 : g_hseq1);
    __shared__ float As[8][128];
    __shared__ float Bs2[8][128];

    int tid  = threadIdx.x;
    int row0 = blockIdx.y * 128;
    int col0 = blockIdx.x * 128;

    ull acc[8][4];
#pragma unroll
    for (int i = 0; i < 8; i++)
#pragma unroll
        for (int j = 0; j < 4; j++) acc[i][j] = 0ull;

    int mb = (tid >> 4) * 8;
    int nb = (tid & 15) * 8;

    int lr = tid >> 1;
    int lk = (tid & 1) * 4;
    int grow = row0 + lr;
    const float* Arow = A + (size_t)(grow >> 6) * stride_t + (size_t)(grow & 63) * stride_b;

    int bk = tid >> 5;
    int bn = (tid & 31) * 4;

    for (int k0 = 0; k0 < K; k0 += 8) {
        float4 av = *(const float4*)(Arow + k0 + lk);
        As[lk + 0][lr] = av.x;
        As[lk + 1][lr] = av.y;
        As[lk + 2][lr] = av.z;
        As[lk + 3][lr] = av.w;
        *(float4*)&Bs2[bk][bn] = *(const float4*)(W + (size_t)(k0 + bk) * FourH + col0 + bn);
        __syncthreads();
#pragma unroll
        for (int k = 0; k < 8; k++) {
            float4 a0 = *(const float4*)&As[k][mb];
            float4 a1 = *(const float4*)&As[k][mb + 4];
            ulonglong2 b0 = *(const ulonglong2*)&Bs2[k][nb];
            ulonglong2 b1 = *(const ulonglong2*)&Bs2[k][nb + 4];
            ull d;
            d = dup2(a0.x); acc[0][0]=fma2(d,b0.x,acc[0][0]); acc[0][1]=fma2(d,b0.y,acc[0][1]); acc[0][2]=fma2(d,b1.x,acc[0][2]); acc[0][3]=fma2(d,b1.y,acc[0][3]);
            d = dup2(a0.y); acc[1][0]=fma2(d,b0.x,acc[1][0]); acc[1][1]=fma2(d,b0.y,acc[1][1]); acc[1][2]=fma2(d,b1.x,acc[1][2]); acc[1][3]=fma2(d,b1.y,acc[1][3]);
            d = dup2(a0.z); acc[2][0]=fma2(d,b0.x,acc[2][0]); acc[2][1]=fma2(d,b0.y,acc[2][1]); acc[2][2]=fma2(d,b1.x,acc[2][2]); acc[2][3]=fma2(d,b1.y,acc[2][3]);
            d = dup2(a0.w); acc[3][0]=fma2(d,b0.x,acc[3][0]); acc[3][1]=fma2(d,b0.y,acc[3][1]); acc[3][2]=fma2(d,b1.x,acc[3][2]); acc[3][3]=fma2(d,b1.y,acc[3][3]);
            d = dup2(a1.x); acc[4][0]=fma2(d,b0.x,acc[4][0]); acc[4][1]=fma2(d,b0.y,acc[4][1]); acc[4][2]=fma2(d,b1.x,acc[4][2]); acc[4][3]=fma2(d,b1.y,acc[4][3]);
            d = dup2(a1.y); acc[5][0]=fma2(d,b0.x,acc[5][0]); acc[5][1]=fma2(d,b0.y,acc[5][1]); acc[5][2]=fma2(d,b1.x,acc[5][2]); acc[5][3]=fma2(d,b1.y,acc[5][3]);
            d = dup2(a1.z); acc[6][0]=fma2(d,b0.x,acc[6][0]); acc[6][1]=fma2(d,b0.y,acc[6][1]); acc[6][2]=fma2(d,b1.x,acc[6][2]); acc[6][3]=fma2(d,b1.y,acc[6][3]);
            d = dup2(a1.w); acc[7][0]=fma2(d,b0.x,acc[7][0]); acc[7][1]=fma2(d,b0.y,acc[7][1]); acc[7][2]=fma2(d,b1.x,acc[7][2]); acc[7][3]=fma2(d,b1.y,acc[7][3]);
        }
        __syncthreads();
    }

    ulonglong2 bb0 = *(const ulonglong2*)&bias[col0 + nb];
    ulonglong2 bb1 = *(const ulonglong2*)&bias[col0 + nb + 4];
#pragma unroll
    for (int i = 0; i < 8; i++) {
        size_t r = (size_t)(row0 + mb + i);
        float* o = g_xproj + r * FourH + col0 + nb;
        ulonglong2 s0, s1;
        s0.x = add2(acc[i][0], bb0.x); s0.y = add2(acc[i][1], bb0.y);
        s1.x = add2(acc[i][2], bb1.x); s1.y = add2(acc[i][3], bb1.y);
        *(ulonglong2*)(o)     = s0;
        *(ulonglong2*)(o + 4) = s1;
    }
}

// ---------------- persistent recurrent layer (f32x2, split-K warps) ----------
// 128 blocks x 256 threads. Block owns 8 h-cols (32 z-cols).
// Warps 0-3: k in [0,512); warps 4-7: k in [512,1024).
// Thread tile: rows {lane, lane+32} x 8 cols (nb = (wid&3)*8).
#define WS_ELEMS (1024 * 32)
#define SHH_ROW  36
#define SHH_HALF (64 * SHH_ROW)
#define SHZ_ROW  36
#define SMEM_ELEMS (WS_ELEMS + 2 * SHH_HALF + 2 * 64 * SHZ_ROW)
#define SMEM_BYTES (SMEM_ELEMS * (int)sizeof(float))

__global__ __launch_bounds__(256) void lstm_layer_persistent(
    const float* __restrict__ Wh, int seqsel, int writeseq)
{
    extern __shared__ float smem[];
    float* w_s   = smem;                       // [1024][32]
    float* sh_h  = w_s + WS_ELEMS;             // [2][64][36]
    float* sh_zA = sh_h + 2 * SHH_HALF;        // [64][36]
    float* sh_zB = sh_zA + 64 * SHZ_ROW;       // [64][36]

    int tid = threadIdx.x;
    int c0  = blockIdx.x * 8;
    unsigned nblk = gridDim.x;

    // load Wh slice: w_s[k*32 + n], n = gate*8 + col
    for (int idx = tid; idx < WS_ELEMS; idx += 256) {
        int k = idx >> 5, n = idx & 31;
        w_s[idx] = Wh[(size_t)k * FourH + (n >> 3) * Hd + c0 + (n & 7)];
    }
    // zero own state columns
    for (int idx = tid; idx < 512; idx += 256) {
        int mm = idx >> 3, col = idx & 7;
        int hi = mm * Hd + c0 + col;
        g_c[hi] = 0.f; g_h0[hi] = 0.f; g_h1[hi] = 0.f;
    }
    unsigned epoch = 0;
    grid_sync(++epoch, nblk);

    float* seq = seqsel ? g_hseq1 : g_hseq0;

    int wid  = tid >> 5;
    int lane = tid & 31;
    int half = wid >> 2;                 // 0 or 1 (K split)
    int nb   = (wid & 3) * 8;            // 8 z-cols
    float* myh = sh_h + half * SHH_HALF;
    float* myz = half ? sh_zB : sh_zA;
    const float* whalf = w_s + (half * 512) * 32;

    // tile loader mapping: per half-tile 512 float4; thread does 2 per half
    int lr  = tid >> 3;                  // 0..31
    int lc4 = (tid & 7) * 4;             // float offset 0..28

    for (int t = 0; t < Tlen; t++) {
        const float* h_in  = (t & 1) ? g_h1 : g_h0;
        float*       h_out = (t & 1) ? g_h0 : g_h1;

        // prefetch tile 0 (k 0..31 and 512..543)
        float4 p0 = *(const float4*)&h_in[lr * Hd + lc4];
        float4 p1 = *(const float4*)&h_in[(lr + 32) * Hd + lc4];
        float4 p2 = *(const float4*)&h_in[lr * Hd + 512 + lc4];
        float4 p3 = *(const float4*)&h_in[(lr + 32) * Hd + 512 + lc4];

        ull acc[2][4];
#pragma unroll
        for (int i = 0; i < 2; i++)
#pragma unroll
            for (int j = 0; j < 4; j++) acc[i][j] = 0ull;

        for (int kt = 0; kt < 16; kt++) {
            *(float4*)&sh_h[lr * SHH_ROW + lc4]                   = p0;
            *(float4*)&sh_h[(lr + 32) * SHH_ROW + lc4]            = p1;
            *(float4*)&sh_h[SHH_HALF + lr * SHH_ROW + lc4]        = p2;
            *(float4*)&sh_h[SHH_HALF + (lr + 32) * SHH_ROW + lc4] = p3;
            __syncthreads();
            if (kt < 15) {
                int kb = (kt + 1) * 32;
                p0 = *(const float4*)&h_in[lr * Hd + kb + lc4];
                p1 = *(const float4*)&h_in[(lr + 32) * Hd + kb + lc4];
                p2 = *(const float4*)&h_in[lr * Hd + 512 + kb + lc4];
                p3 = *(const float4*)&h_in[(lr + 32) * Hd + 512 + kb + lc4];
            }
            const float* wbase = whalf + (kt * 32) * 32 + nb;
#pragma unroll
            for (int kk = 0; kk < 32; kk += 4) {
                float4 alo = *(const float4*)&myh[lane * SHH_ROW + kk];
                float4 ahi = *(const float4*)&myh[(lane + 32) * SHH_ROW + kk];
#pragma unroll
                for (int j = 0; j < 4; j++) {
                    float alj = (j == 0) ? alo.x : (j == 1) ? alo.y : (j == 2) ? alo.z : alo.w;
                    float ahj = (j == 0) ? ahi.x : (j == 1) ? ahi.y : (j == 2) ? ahi.z : ahi.w;
                    ull a0 = dup2(alj);
                    ull a1 = dup2(ahj);
                    const float* wp = wbase + (kk + j) * 32;
                    ulonglong2 bA = *(const ulonglong2*)(wp);
                    ulonglong2 bB = *(const ulonglong2*)(wp + 4);
                    acc[0][0] = fma2(a0, bA.x, acc[0][0]);
                    acc[0][1] = fma2(a0, bA.y, acc[0][1]);
                    acc[0][2] = fma2(a0, bB.x, acc[0][2]);
                    acc[0][3] = fma2(a0, bB.y, acc[0][3]);
                    acc[1][0] = fma2(a1, bA.x, acc[1][0]);
                    acc[1][1] = fma2(a1, bA.y, acc[1][1]);
                    acc[1][2] = fma2(a1, bB.x, acc[1][2]);
                    acc[1][3] = fma2(a1, bB.y, acc[1][3]);
                }
            }
            __syncthreads();
        }

        // write partials to half buffer
#pragma unroll
        for (int cp = 0; cp < 4; cp++) {
            float z0, z1;
            unpack2(acc[0][cp], z0, z1);
            myz[lane * SHZ_ROW + nb + 2 * cp]     = z0;
            myz[lane * SHZ_ROW + nb + 2 * cp + 1] = z1;
            unpack2(acc[1][cp], z0, z1);
            myz[(lane + 32) * SHZ_ROW + nb + 2 * cp]     = z0;
            myz[(lane + 32) * SHZ_ROW + nb + 2 * cp + 1] = z1;
        }
        __syncthreads();

        // gate phase: 512 (row,col) items, 2 per thread
#pragma unroll
        for (int p = 0; p < 2; p++) {
            int idx = tid * 2 + p;
            int col = idx & 7;
            int mm  = idx >> 3;
            const float* xp = g_xproj + (size_t)(t * Bsz + mm) * FourH + c0 + col;
            const float* zA = sh_zA + mm * SHZ_ROW;
            const float* zB = sh_zB + mm * SHZ_ROW;
            float zi = zA[col]      + zB[col]      + xp[0];
            float zf = zA[8 + col]  + zB[8 + col]  + xp[Hd];
            float zg = zA[16 + col] + zB[16 + col] + xp[2 * Hd];
            float zo = zA[24 + col] + zB[24 + col] + xp[3 * Hd];

            int hi = mm * Hd + c0 + col;
            float co = g_c[hi];
            float si = sigmoid_f(zi);
            float sf = sigmoid_f(zf);
            float so = sigmoid_f(zo);
            float tg = tanh_f(zg);
            float cn = sf * co + si * tg;
            float hn = so * tanh_f(cn);

            g_c[hi]   = cn;
            h_out[hi] = hn;
            if (writeseq)
                seq[(size_t)(t * Bsz + mm) * Hd + c0 + col] = hn;
        }
        grid_sync(++epoch, nblk);
    }
}

// ---------------- head ----------------
__global__ void head_kernel(const float* __restrict__ Wc, const float* __restrict__ bc,
                            float* __restrict__ out)
{
    int b = blockIdx.x;
    int w = threadIdx.x >> 5;
    int lane = threadIdx.x & 31;
    const float* h = g_h0 + b * Hd;   // t=255 (odd) writes buffer 0
    float s = 0.f;
    for (int k = lane; k < Hd; k += 32) s += h[k] * Wc[k * Cd + w];
#pragma unroll
    for (int o = 16; o > 0; o >>= 1) s += __shfl_down_sync(0xffffffffu, s, o);
    if (lane == 0) out[b * Cd + w] = s + bc[w];
}

// ---------------- launch ----------------
extern "C" void kernel_launch(void* const* d_in, const int* in_sizes, int n_in,
                              void* d_out, int out_size)
{
    const float* x    = (const float*)d_in[0];
    const float* Wx0  = (const float*)d_in[1];
    const float* Wxs  = (const float*)d_in[2];
    const float* Whs  = (const float*)d_in[3];
    const float* bs   = (const float*)d_in[4];
    const float* Wc   = (const float*)d_in[5];
    const float* bc   = (const float*)d_in[6];
    float* out = (float*)d_out;

    cudaFuncSetAttribute(lstm_layer_persistent,
                         cudaFuncAttributeMaxDynamicSharedMemorySize, SMEM_BYTES);

    void* bar_addr = nullptr;
    cudaGetSymbolAddress(&bar_addr, g_bar);

    dim3 pgrid(FourH / 128, Mrows / 128);   // 32 x 128

    for (int l = 0; l < Ld; l++) {
        int src = (l == 0) ? 0 : ((((l - 1) & 1) == 0) ? 1 : 2);
        const float* W = (l == 0) ? Wx0 : (Wxs + (size_t)(l - 1) * Hd * FourH);
        int K  = (l == 0) ? Din : Hd;
        int st = (l == 0) ? Din : Bsz * Hd;
        int sb = (l == 0) ? Tlen * Din : Hd;

        proj_gemm<<<pgrid, 256>>>(x, src, st, sb, K, W, bs + (size_t)l * FourH);

        cudaMemsetAsync(bar_addr, 0, 2 * sizeof(unsigned));

        const float* Wh = Whs + (size_t)l * Hd * FourH;
        lstm_layer_persistent<<<128, 256, SMEM_BYTES>>>(Wh, l & 1, (l < Ld - 1) ? 1 : 0);
    }

    head_kernel<<<Bsz, 320>>>(Wc, bc, out);
}

// round 4
// speedup vs baseline: 3.1695x; 2.1382x over previous
#include <cuda_runtime.h>
#include <math.h>
#include <stdint.h>

#define Bsz   64
#define Tlen  256
#define Din   128
#define Hd    1024
#define Ld    5
#define Cd    10
#define FourH 4096
#define Mrows (Tlen * Bsz)   // 16384

// ---------------- scratch (static device globals; no allocs) ----------------
// xproj layout is GATE-INTERLEAVED: xproj[row][hcol][gate], gate order i,f,g,o
__device__ float g_xproj[(size_t)Mrows * FourH];   // 256 MB
__device__ float g_hseq0[(size_t)Mrows * Hd];      // 64 MB
__device__ float g_hseq1[(size_t)Mrows * Hd];      // 64 MB
__device__ float g_h0[Bsz * Hd];
__device__ float g_h1[Bsz * Hd];
__device__ float g_c[Bsz * Hd];
__device__ unsigned g_bar[2];                      // [0]=arrive, [1]=release

// ---------------- PTX helpers ----------------
__device__ __forceinline__ uint32_t f2tf32(float f) {
    uint32_t u; asm("cvt.rna.tf32.f32 %0, %1;" : "=r"(u) : "f"(f)); return u;
}
__device__ __forceinline__ void ldsm_x4(uint32_t& r0, uint32_t& r1, uint32_t& r2,
                                        uint32_t& r3, uint32_t addr) {
    asm volatile("ldmatrix.sync.aligned.m8n8.x4.shared.b16 {%0,%1,%2,%3}, [%4];"
                 : "=r"(r0), "=r"(r1), "=r"(r2), "=r"(r3) : "r"(addr));
}
__device__ __forceinline__ void mma_tf32(float* d, uint32_t a0, uint32_t a1,
                                         uint32_t a2, uint32_t a3,
                                         uint32_t b0, uint32_t b1) {
    asm volatile("mma.sync.aligned.m16n8k8.row.col.f32.tf32.tf32.f32 "
                 "{%0,%1,%2,%3}, {%4,%5,%6,%7}, {%8,%9}, {%0,%1,%2,%3};"
                 : "+f"(d[0]), "+f"(d[1]), "+f"(d[2]), "+f"(d[3])
                 : "r"(a0), "r"(a1), "r"(a2), "r"(a3), "r"(b0), "r"(b1));
}

// ---------------- software grid barrier ----------------
__device__ __forceinline__ void grid_sync(unsigned epoch, unsigned nblk) {
    __syncthreads();
    if (threadIdx.x == 0) {
        __threadfence();
        unsigned prev = atomicAdd(&g_bar[0], 1u);
        if (prev == nblk * epoch - 1u) {
            asm volatile("st.release.gpu.global.u32 [%0], %1;" :: "l"(&g_bar[1]), "r"(epoch) : "memory");
        } else {
            unsigned v;
            do {
                asm volatile("ld.acquire.gpu.global.u32 %0, [%1];" : "=r"(v) : "l"(&g_bar[1]) : "memory");
            } while (v < epoch);
        }
    }
    __syncthreads();
}

// ---------------- fast activations ----------------
__device__ __forceinline__ float sigmoid_f(float x) {
    return __fdividef(1.f, 1.f + __expf(-x));
}
__device__ __forceinline__ float tanh_f(float x) {
    float e = __expf(2.f * x);
    return 1.f - __fdividef(2.f, e + 1.f);
}

// ============================================================================
// Input projection GEMM (tf32 tensor cores)
//   out[row][hcol][gate] = bias[n] + sum_k A[row][k] * W[k][n],  n = gate*1024+hcol
//   Block tile 128x128, k-tile 32. 256 threads = 8 warps (2 m-groups x 4 n-groups).
//   Warp tile 64x32: 4 m16-tiles x 4 n8-tiles. K inner step 8.
// smem: As[128][36] (m-major, tf32 bits) | Bs[32][136] (k-major, tf32 bits)
// ============================================================================
#define PA_PITCH 36
#define PB_PITCH 136
#define PROJ_SMEM ((128 * PA_PITCH + 32 * PB_PITCH) * 4)

__global__ __launch_bounds__(256) void proj_gemm_tc(
    const float* __restrict__ x_ext, int src_sel,
    int stride_t, int stride_b, int K,
    const float* __restrict__ W, const float* __restrict__ bias)
{
    const float* A = (src_sel == 0) ? x_ext : (src_sel == 1 ? g_hseq0 : g_hseq1);
    extern __shared__ uint32_t ps[];
    uint32_t* As = ps;                      // 128 x 36
    uint32_t* Bs = ps + 128 * PA_PITCH;     // 32 x 136
    uint32_t sbase = (uint32_t)__cvta_generic_to_shared(ps);

    int tid  = threadIdx.x;
    int wid  = tid >> 5;
    int lane = tid & 31;
    int row0 = blockIdx.y * 128;
    int col0 = blockIdx.x * 128;

    int wm = wid & 1;          // m-group (64 rows each)
    int wn = wid >> 1;         // n-group (32 cols each)

    // A stage mapping: pass p: row = p*32 + wid*4 + lane/8, k4 = 4*(lane&7)
    int a_rl   = wid * 4 + (lane >> 3);
    int a_k4   = (lane & 7) * 4;
    // B stage mapping: pass p: k = p*8 + wid, n4 = lane*4
    int b_n4   = lane * 4;

    // ldmatrix per-lane address components
    int lm_row = (lane & 7) + ((lane >> 3) & 1) * 8;
    int lm_k   = (lane >> 4) * 4;

    // precompute global A row pointers (4 passes)
    const float* Arow[4];
#pragma unroll
    for (int p = 0; p < 4; p++) {
        int gr = row0 + p * 32 + a_rl;
        Arow[p] = A + (size_t)(gr >> 6) * stride_t + (size_t)(gr & 63) * stride_b;
    }

    float acc[4][4][4];
#pragma unroll
    for (int i = 0; i < 4; i++)
#pragma unroll
        for (int j = 0; j < 4; j++)
#pragma unroll
            for (int r = 0; r < 4; r++) acc[i][j][r] = 0.f;

    // prefetch tile 0
    float4 pa[4], pb[4];
#pragma unroll
    for (int p = 0; p < 4; p++) pa[p] = *(const float4*)(Arow[p] + a_k4);
#pragma unroll
    for (int p = 0; p < 4; p++)
        pb[p] = *(const float4*)(W + (size_t)(p * 8 + wid) * FourH + col0 + b_n4);

    int ntiles = K >> 5;
    for (int kt = 0; kt < ntiles; kt++) {
        // store staged tile (convert to tf32)
#pragma unroll
        for (int p = 0; p < 4; p++) {
            uint32_t* d = As + (p * 32 + a_rl) * PA_PITCH + a_k4;
            uint4 v = { f2tf32(pa[p].x), f2tf32(pa[p].y), f2tf32(pa[p].z), f2tf32(pa[p].w) };
            *(uint4*)d = v;
        }
#pragma unroll
        for (int p = 0; p < 4; p++) {
            uint32_t* d = Bs + (p * 8 + wid) * PB_PITCH + b_n4;
            uint4 v = { f2tf32(pb[p].x), f2tf32(pb[p].y), f2tf32(pb[p].z), f2tf32(pb[p].w) };
            *(uint4*)d = v;
        }
        __syncthreads();

        if (kt + 1 < ntiles) {
            int kb = (kt + 1) * 32;
#pragma unroll
            for (int p = 0; p < 4; p++) pa[p] = *(const float4*)(Arow[p] + kb + a_k4);
#pragma unroll
            for (int p = 0; p < 4; p++)
                pb[p] = *(const float4*)(W + (size_t)(kb + p * 8 + wid) * FourH + col0 + b_n4);
        }

#pragma unroll
        for (int kk = 0; kk < 4; kk++) {
            // B fragments: 4 n-tiles x 2 regs (conflict-free LDS)
            uint32_t bf[4][2];
#pragma unroll
            for (int nt = 0; nt < 4; nt++) {
                const uint32_t* bp = Bs + (kk * 8 + (lane & 3)) * PB_PITCH
                                     + wn * 32 + nt * 8 + (lane >> 2);
                bf[nt][0] = bp[0];
                bf[nt][1] = bp[4 * PB_PITCH];
            }
            // A fragments + mma
#pragma unroll
            for (int mt = 0; mt < 4; mt++) {
                uint32_t a0, a1, a2, a3;
                uint32_t addr = sbase +
                    ((wm * 64 + mt * 16 + lm_row) * PA_PITCH + kk * 8 + lm_k) * 4;
                ldsm_x4(a0, a1, a2, a3, addr);
#pragma unroll
                for (int nt = 0; nt < 4; nt++)
                    mma_tf32(acc[mt][nt], a0, a1, a2, a3, bf[nt][0], bf[nt][1]);
            }
        }
        __syncthreads();
    }

    // epilogue: add bias, store gate-interleaved
    int gate  = col0 >> 10;
    int hbase = col0 & 1023;
#pragma unroll
    for (int mt = 0; mt < 4; mt++) {
        int row = row0 + wm * 64 + mt * 16 + (lane >> 2);
#pragma unroll
        for (int nt = 0; nt < 4; nt++) {
            int nl = wn * 32 + nt * 8 + 2 * (lane & 3);
            float b0v = bias[col0 + nl];
            float b1v = bias[col0 + nl + 1];
            int hcol = hbase + nl;
            float* o0 = g_xproj + (size_t)row * FourH + hcol * 4 + gate;
            o0[0] = acc[mt][nt][0] + b0v;
            o0[4] = acc[mt][nt][1] + b1v;
            float* o1 = o0 + (size_t)8 * FourH;
            o1[0] = acc[mt][nt][2] + b0v;
            o1[4] = acc[mt][nt][3] + b1v;
        }
    }
}

// ============================================================================
// Persistent recurrent layer (tf32 tensor cores, weights in registers)
//   128 blocks x 512 threads. Block owns 8 h-cols => 32 z-cols (4 gates x 8).
//   16 warps = (gate g = wid&3) x (k-split s = wid>>2, K range 256 each).
//   Warp tile: m64 x n8 x k256, B (Wh slice) held in 64 regs as tf32.
// smem: sA[4][64][36] (staged h, tf32 bits) | pD[4][64][36] (k-split partials)
// ============================================================================
#define RPITCH 36
#define RSEG   (64 * RPITCH)           // 2304
#define REC_SMEM (2 * 4 * RSEG * 4)    // 73728 B

__global__ __launch_bounds__(512) void lstm_layer_tc(
    const float* __restrict__ Wh, int seqsel, int writeseq)
{
    extern __shared__ uint32_t rs[];
    uint32_t* sA = rs;                       // 4 * 2304
    float*    pD = (float*)(rs + 4 * RSEG);  // 4 * 2304
    uint32_t sAbase = (uint32_t)__cvta_generic_to_shared(rs);

    int tid  = threadIdx.x;
    int wid  = tid >> 5;
    int lane = tid & 31;
    int g    = wid & 3;        // gate / n-group
    int s    = wid >> 2;       // k-split (256 K each)
    int c0   = blockIdx.x * 8;
    unsigned nblk = gridDim.x;

    // ---- load Wh slice into registers as tf32 B-fragments ----
    uint32_t b0[32], b1[32];
    {
        const float* Wb = Wh + (size_t)(s * 256) * FourH + g * Hd + c0 + (lane >> 2);
#pragma unroll
        for (int j = 0; j < 32; j++) {
            int k = j * 8 + (lane & 3);
            b0[j] = f2tf32(Wb[(size_t)k * FourH]);
            b1[j] = f2tf32(Wb[(size_t)(k + 4) * FourH]);
        }
    }

    // ---- zero own state columns (one item per thread) ----
    {
        int m = tid >> 3, hc = tid & 7;
        int hi = m * Hd + c0 + hc;
        g_c[hi] = 0.f; g_h0[hi] = 0.f; g_h1[hi] = 0.f;
    }
    unsigned epoch = 0;
    grid_sync(++epoch, nblk);

    float* seq = seqsel ? g_hseq1 : g_hseq0;

    // staging map: warp wid stages rows wid*4 + lane/8, k4 = 4*(lane&7)
    int srow = wid * 4 + (lane >> 3);
    int sk4  = (lane & 7) * 4;
    // ldmatrix lane components
    int lm_row = (lane & 7) + ((lane >> 3) & 1) * 8;
    int lm_k   = (lane >> 4) * 4;
    // gate-phase item
    int gm = tid >> 3, ghc = tid & 7;
    int ghi = gm * Hd + c0 + ghc;

    for (int t = 0; t < Tlen; t++) {
        const float* h_in  = (t & 1) ? g_h1 : g_h0;
        float*       h_out = (t & 1) ? g_h0 : g_h1;

        float4 pf[4];
#pragma unroll
        for (int sp = 0; sp < 4; sp++)
            pf[sp] = *(const float4*)&h_in[srow * Hd + sp * 256 + sk4];

        float acc[4][4];
#pragma unroll
        for (int mt = 0; mt < 4; mt++)
#pragma unroll
            for (int r = 0; r < 4; r++) acc[mt][r] = 0.f;

        for (int kt = 0; kt < 8; kt++) {
            // stage (convert to tf32), conflict-free 16B stores
#pragma unroll
            for (int sp = 0; sp < 4; sp++) {
                uint32_t* d = sA + sp * RSEG + srow * RPITCH + sk4;
                uint4 v = { f2tf32(pf[sp].x), f2tf32(pf[sp].y),
                            f2tf32(pf[sp].z), f2tf32(pf[sp].w) };
                *(uint4*)d = v;
            }
            __syncthreads();

            if (kt < 7) {
                int kb = (kt + 1) * 32;
#pragma unroll
                for (int sp = 0; sp < 4; sp++)
                    pf[sp] = *(const float4*)&h_in[srow * Hd + sp * 256 + kb + sk4];
            }

#pragma unroll
            for (int kk = 0; kk < 4; kk++) {
                int j = kt * 4 + kk;
#pragma unroll
                for (int mt = 0; mt < 4; mt++) {
                    uint32_t a0, a1, a2, a3;
                    uint32_t addr = sAbase +
                        (s * RSEG + (mt * 16 + lm_row) * RPITCH + kk * 8 + lm_k) * 4;
                    ldsm_x4(a0, a1, a2, a3, addr);
                    mma_tf32(acc[mt], a0, a1, a2, a3, b0[j], b1[j]);
                }
            }
            __syncthreads();
        }

        // write k-split partials
#pragma unroll
        for (int mt = 0; mt < 4; mt++) {
            int row = mt * 16 + (lane >> 2);
            float* p = pD + s * RSEG + row * RPITCH + g * 8 + 2 * (lane & 3);
            p[0] = acc[mt][0];
            p[1] = acc[mt][1];
            p[8 * RPITCH]     = acc[mt][2];
            p[8 * RPITCH + 1] = acc[mt][3];
        }
        __syncthreads();

        // fused gate phase: 512 items, 1 per thread
        {
            float4 xp = *(const float4*)&g_xproj[((size_t)(t * Bsz + gm)) * FourH
                                                 + (c0 + ghc) * 4];
            float zi = xp.x, zf = xp.y, zg = xp.z, zo = xp.w;
#pragma unroll
            for (int sp = 0; sp < 4; sp++) {
                const float* q = pD + sp * RSEG + gm * RPITCH;
                zi += q[ghc];
                zf += q[8 + ghc];
                zg += q[16 + ghc];
                zo += q[24 + ghc];
            }
            float co = g_c[ghi];
            float si = sigmoid_f(zi);
            float sf = sigmoid_f(zf);
            float so = sigmoid_f(zo);
            float tg = tanh_f(zg);
            float cn = sf * co + si * tg;
            float hn = so * tanh_f(cn);
            g_c[ghi]   = cn;
            h_out[ghi] = hn;
            if (writeseq)
                seq[((size_t)(t * Bsz + gm)) * Hd + c0 + ghc] = hn;
        }
        grid_sync(++epoch, nblk);
    }
}

// ---------------- head ----------------
__global__ void head_kernel(const float* __restrict__ Wc, const float* __restrict__ bc,
                            float* __restrict__ out)
{
    int b = blockIdx.x;
    int w = threadIdx.x >> 5;
    int lane = threadIdx.x & 31;
    const float* h = g_h0 + b * Hd;   // t=255 (odd) writes buffer 0
    float s = 0.f;
    for (int k = lane; k < Hd; k += 32) s += h[k] * Wc[k * Cd + w];
#pragma unroll
    for (int o = 16; o > 0; o >>= 1) s += __shfl_down_sync(0xffffffffu, s, o);
    if (lane == 0) out[b * Cd + w] = s + bc[w];
}

// ---------------- launch ----------------
extern "C" void kernel_launch(void* const* d_in, const int* in_sizes, int n_in,
                              void* d_out, int out_size)
{
    const float* x    = (const float*)d_in[0];
    const float* Wx0  = (const float*)d_in[1];
    const float* Wxs  = (const float*)d_in[2];
    const float* Whs  = (const float*)d_in[3];
    const float* bs   = (const float*)d_in[4];
    const float* Wc   = (const float*)d_in[5];
    const float* bc   = (const float*)d_in[6];
    float* out = (float*)d_out;

    cudaFuncSetAttribute(proj_gemm_tc,
                         cudaFuncAttributeMaxDynamicSharedMemorySize, PROJ_SMEM);
    cudaFuncSetAttribute(lstm_layer_tc,
                         cudaFuncAttributeMaxDynamicSharedMemorySize, REC_SMEM);

    void* bar_addr = nullptr;
    cudaGetSymbolAddress(&bar_addr, g_bar);

    dim3 pgrid(FourH / 128, Mrows / 128);   // 32 x 128

    for (int l = 0; l < Ld; l++) {
        int src = (l == 0) ? 0 : ((((l - 1) & 1) == 0) ? 1 : 2);
        const float* W = (l == 0) ? Wx0 : (Wxs + (size_t)(l - 1) * Hd * FourH);
        int K  = (l == 0) ? Din : Hd;
        int st = (l == 0) ? Din : Bsz * Hd;
        int sb = (l == 0) ? Tlen * Din : Hd;

        proj_gemm_tc<<<pgrid, 256, PROJ_SMEM>>>(x, src, st, sb, K, W,
                                                bs + (size_t)l * FourH);

        cudaMemsetAsync(bar_addr, 0, 2 * sizeof(unsigned));

        const float* Wh = Whs + (size_t)l * Hd * FourH;
        lstm_layer_tc<<<128, 512, REC_SMEM>>>(Wh, l & 1, (l < Ld - 1) ? 1 : 0);
    }

    head_kernel<<<Bsz, 320>>>(Wc, bc, out);
}